// round 12
// baseline (speedup 1.0000x reference)
#include <cuda_runtime.h>

#define TPB 256

constexpr int B_     = 16384;
constexpr int N_     = 70;
constexpr int E_     = 3;
constexpr int S_     = 10;
constexpr int STEPS_ = 5;
constexpr int BB_    = 16;            // batch elements per CTA
constexpr int XST_   = 82;            // X row stride in u64 (padded; 80 used)

// ---- shared memory layout (float offsets) ----
constexpr int OFF_X    = 0;                      // 70*82 u64 = 11480 fl
constexpr int OFF_P    = 11480;                  // 10 planes * 1120 = 11200
constexpr int OFF_AS   = 22680;                  // full e-slice: 70*70 = 4900
constexpr int OFF_WIN2 = 27580;                  // [e][d][6] f2 = 360
constexpr int OFF_BIN2 = 27940;                  // 30 (+2 pad)
constexpr int OFF_WR2  = 27972;                  // [j][6] f2 = 240
constexpr int OFF_BR2  = 28212;                  // 10 (+2 pad)
constexpr int OFF_WZ2  = 28224;                  // 240
constexpr int OFF_BZ2  = 28464;                  // 10 (+2 pad)
constexpr int OFF_WH2  = 28476;                  // 240
constexpr int OFF_BH2  = 28716;                  // 10
constexpr int OFF_WO1  = 28726;                  // 110
constexpr int OFF_BO1  = 28836;                  // 10
constexpr int OFF_WO2  = 28846;                  // 10
constexpr int OFF_BO2  = 28856;                  // 1
constexpr int SMEM_FLOATS = 28857;               // 115428 B/CTA -> 2 CTAs/SM

typedef unsigned long long u64;

__device__ __forceinline__ u64 ffma2(u64 a, u64 b, u64 c) {
    u64 d;
    asm("fma.rn.f32x2 %0, %1, %2, %3;" : "=l"(d) : "l"(a), "l"(b), "l"(c));
    return d;
}
__device__ __forceinline__ u64 pack2(float x) {
    u64 d;
    asm("mov.b64 %0, {%1, %1};" : "=l"(d) : "f"(x));
    return d;
}
__device__ __forceinline__ void unpack2(u64 v, float& x, float& y) {
    asm("mov.b64 {%0, %1}, %2;" : "=f"(x), "=f"(y) : "l"(v));
}

__device__ __forceinline__ float sigf(float x) {
    return __fdividef(1.0f, 1.0f + __expf(-x));
}
__device__ __forceinline__ float tanh_(float x) {
    float e = __expf(-2.0f * x);
    return __fdividef(1.0f - e, 1.0f + e);
}

extern __shared__ float sm[];

// ---- stage A[:, e*70 : (e+1)*70] into SMEM (contiguous 70x70) ----
__device__ __forceinline__ void stageA(const float* __restrict__ Ag, int e,
                                       int t) {
#pragma unroll 1
    for (int i = t; i < 70 * 70; i += TPB) {
        int row = i / 70, kk = i - row * 70;
        sm[OFF_AS + i] = Ag[row * 210 + e * 70 + kk];
    }
}

// ---- load both X rows (even/odd k) for one k2 into a 10-u64 buffer ----
__device__ __forceinline__ void loadX(u64 (&b)[10], const u64* xE, int tx) {
    const u64* xO = xE + XST_;
    ulonglong2 p;
    p = *(const ulonglong2*)(xE + 4 * tx);     b[0] = p.x; b[1] = p.y;
    p = *(const ulonglong2*)(xE + 4 * tx + 2); b[2] = p.x; b[3] = p.y;
    b[4] = xE[64 + tx];
    p = *(const ulonglong2*)(xO + 4 * tx);     b[5] = p.x; b[6] = p.y;
    p = *(const ulonglong2*)(xO + 4 * tx + 2); b[7] = p.x; b[8] = p.y;
    b[9] = xO[64 + tx];
}

// ---- one k2 of FFMA2 work against a preloaded X buffer ----
// rows ty+16i (i=0..3) always; row 64+ty only when R==5 (warp-uniform).
template <int R>
__device__ __forceinline__ void computeK(u64 (&acc)[5][5], const u64 (&b)[10],
                                         const u64* A64, int rbase, int k2) {
#pragma unroll
    for (int i = 0; i < 4; ++i) {
        u64 a2 = A64[rbase + i * 560 + k2];
        float lo, hi;
        unpack2(a2, lo, hi);
        u64 pE = pack2(lo);
        acc[i][0] = ffma2(pE, b[0], acc[i][0]);
        acc[i][1] = ffma2(pE, b[1], acc[i][1]);
        acc[i][2] = ffma2(pE, b[2], acc[i][2]);
        acc[i][3] = ffma2(pE, b[3], acc[i][3]);
        acc[i][4] = ffma2(pE, b[4], acc[i][4]);
        u64 pO = pack2(hi);
        acc[i][0] = ffma2(pO, b[5], acc[i][0]);
        acc[i][1] = ffma2(pO, b[6], acc[i][1]);
        acc[i][2] = ffma2(pO, b[7], acc[i][2]);
        acc[i][3] = ffma2(pO, b[8], acc[i][3]);
        acc[i][4] = ffma2(pO, b[9], acc[i][4]);
    }
    if (R == 5) {
        u64 a2 = A64[rbase + 2240 + k2];   // row 64+ty
        float lo, hi;
        unpack2(a2, lo, hi);
        u64 pE = pack2(lo);
        acc[4][0] = ffma2(pE, b[0], acc[4][0]);
        acc[4][1] = ffma2(pE, b[1], acc[4][1]);
        acc[4][2] = ffma2(pE, b[2], acc[4][2]);
        acc[4][3] = ffma2(pE, b[3], acc[4][3]);
        acc[4][4] = ffma2(pE, b[4], acc[4][4]);
        u64 pO = pack2(hi);
        acc[4][0] = ffma2(pO, b[5], acc[4][0]);
        acc[4][1] = ffma2(pO, b[6], acc[4][1]);
        acc[4][2] = ffma2(pO, b[7], acc[4][2]);
        acc[4][3] = ffma2(pO, b[8], acc[4][3]);
        acc[4][4] = ffma2(pO, b[9], acc[4][4]);
    }
}

// ---- full-e GEMM, X software-pipelined with a 2-deep ping-pong buffer ----
template <int R>
__device__ __forceinline__ void gemm_full(u64 (&acc)[5][5], const u64* Xb,
                                          int tx, int ty) {
    const u64* A64 = (const u64*)(sm + OFF_AS);
    const int rbase = ty * 35;
    u64 b0[10], b1[10];
    loadX(b0, Xb, tx);
#pragma unroll 1
    for (int k2 = 0; k2 < 34; k2 += 2) {
        loadX(b1, Xb + (2 * (k2 + 1)) * XST_, tx);
        computeK<R>(acc, b0, A64, rbase, k2);
        loadX(b0, Xb + (2 * (k2 + 2)) * XST_, tx);
        computeK<R>(acc, b1, A64, rbase, k2 + 1);
    }
    computeK<R>(acc, b0, A64, rbase, 34);
}

__global__ void __launch_bounds__(TPB, 2) ggnn_kernel(
    const float* __restrict__ annotation, const float* __restrict__ Ag,
    const float* __restrict__ W_in, const float* __restrict__ b_in,
    const float* __restrict__ Wr, const float* __restrict__ br,
    const float* __restrict__ Wz, const float* __restrict__ bz,
    const float* __restrict__ Wh, const float* __restrict__ bh,
    const float* __restrict__ Wo1, const float* __restrict__ bo1,
    const float* __restrict__ Wo2, const float* __restrict__ bo2,
    float* __restrict__ out)
{
    const int t  = threadIdx.x;
    const int b0i = blockIdx.x * BB_;

    // ---- stage paired weight tables ----
    for (int i = t; i < 150; i += TPB) {      // WIN2 [e][d][6]
        int s2 = i % 5, d = (i / 5) % 10, e = i / 50;
        ((float2*)(sm + OFF_WIN2))[e * 60 + d * 6 + s2] =
            make_float2(W_in[(e * 10 + 2 * s2) * 10 + d],
                        W_in[(e * 10 + 2 * s2 + 1) * 10 + d]);
    }
    if (t < 15) {                             // BIN2 [e][s2]
        int s2 = t % 5, e = t / 5;
        ((float2*)(sm + OFF_BIN2))[t] =
            make_float2(b_in[e * 10 + 2 * s2], b_in[e * 10 + 2 * s2 + 1]);
    }
    for (int i = t; i < 100; i += TPB) {      // W{r,z,h}2 [j][6]
        int s2 = i % 5, j = i / 5;
        ((float2*)(sm + OFF_WR2))[j * 6 + s2] =
            make_float2(Wr[2 * s2 * 20 + j], Wr[(2 * s2 + 1) * 20 + j]);
        ((float2*)(sm + OFF_WZ2))[j * 6 + s2] =
            make_float2(Wz[2 * s2 * 20 + j], Wz[(2 * s2 + 1) * 20 + j]);
        ((float2*)(sm + OFF_WH2))[j * 6 + s2] =
            make_float2(Wh[2 * s2 * 20 + j], Wh[(2 * s2 + 1) * 20 + j]);
    }
    if (t < 5) {
        ((float2*)(sm + OFF_BR2))[t] = make_float2(br[2 * t], br[2 * t + 1]);
        ((float2*)(sm + OFF_BZ2))[t] = make_float2(bz[2 * t], bz[2 * t + 1]);
        ((float2*)(sm + OFF_BH2))[t] = make_float2(bh[2 * t], bh[2 * t + 1]);
    }
    for (int i = t; i < 110; i += TPB) sm[OFF_WO1 + i] = Wo1[i];
    if (t < 10) { sm[OFF_BO1 + t] = bo1[t]; sm[OFF_WO2 + t] = Wo2[t]; }
    if (t == 0) sm[OFF_BO2] = bo2[0];

    // ---- prop init: P[0][idx] = ann, P[1..9][idx] = 0 ----
    for (int i = t; i < BB_ * N_; i += TPB) {
        float a = annotation[b0i * N_ + i];
        sm[OFF_P + i] = a;
#pragma unroll
        for (int d = 1; d < S_; ++d) sm[OFF_P + d * 1120 + i] = 0.0f;
    }
    __syncthreads();

    const int tx = t & 15;   // column group (0..15) — warp-varying
    const int ty = t >> 4;   // row group (0..15)    — warp-uniform pairs
    const bool has5 = (ty < 6);   // warp-uniform (ty pairs {0,1},{2,3},...)

    u64 acc[5][5];

#pragma unroll 1
    for (int step = 0; step < STEPS_; ++step) {
#pragma unroll
        for (int i = 0; i < 5; ++i)
#pragma unroll
            for (int j = 0; j < 5; ++j) acc[i][j] = 0ull;

#pragma unroll 1
        for (int e = 0; e < 3; ++e) {
            // ---- stage full A slice + build X (disjoint writes, one phase) --
            stageA(Ag, e, t);
#pragma unroll 1
            for (int task = t; task < BB_ * N_; task += TPB) {
                int bb = task & 15, n = task >> 4;
                int idx = bb * N_ + n;
                const u64* B2 = (const u64*)(sm + OFF_BIN2) + e * 5;
                u64 a0 = B2[0], a1 = B2[1], a2 = B2[2], a3 = B2[3], a4 = B2[4];
                const float* Wb = sm + OFF_WIN2 + e * 120;
#pragma unroll
                for (int d = 0; d < 10; ++d) {
                    u64 p2 = pack2(sm[OFF_P + d * 1120 + idx]);
                    ulonglong2 wa = *(const ulonglong2*)(Wb + d * 12);
                    ulonglong2 wb = *(const ulonglong2*)(Wb + d * 12 + 4);
                    u64 wc = *(const u64*)(Wb + d * 12 + 8);
                    a0 = ffma2(p2, wa.x, a0);
                    a1 = ffma2(p2, wa.y, a1);
                    a2 = ffma2(p2, wb.x, a2);
                    a3 = ffma2(p2, wb.y, a3);
                    a4 = ffma2(p2, wc, a4);
                }
                u64* xo = (u64*)(sm + OFF_X) + n * XST_ + bb * 5;
                xo[0] = a0; xo[1] = a1; xo[2] = a2; xo[3] = a3; xo[4] = a4;
            }
            __syncthreads();

            if (has5) gemm_full<5>(acc, (const u64*)(sm + OFF_X), tx, ty);
            else      gemm_full<4>(acc, (const u64*)(sm + OFF_X), tx, ty);
            __syncthreads();
        }

        // ---- write a_in back into X (rows < 70 only) ----
        {
            u64* X64 = (u64*)(sm + OFF_X);
#pragma unroll
            for (int i = 0; i < 4; ++i) {
                u64* xo = X64 + (ty + 16 * i) * XST_;
                ulonglong2 v0; v0.x = acc[i][0]; v0.y = acc[i][1];
                ulonglong2 v1; v1.x = acc[i][2]; v1.y = acc[i][3];
                *(ulonglong2*)(xo + 4 * tx) = v0;
                *(ulonglong2*)(xo + 4 * tx + 2) = v1;
                xo[64 + tx] = acc[i][4];
            }
            if (has5) {
                u64* xo = X64 + (64 + ty) * XST_;
                ulonglong2 v0; v0.x = acc[4][0]; v0.y = acc[4][1];
                ulonglong2 v1; v1.x = acc[4][2]; v1.y = acc[4][3];
                *(ulonglong2*)(xo + 4 * tx) = v0;
                *(ulonglong2*)(xo + 4 * tx + 2) = v1;
                xo[64 + tx] = acc[4][4];
            }
        }
        __syncthreads();

        // ---- gates: 2 batch elements per task ----
#pragma unroll 1
        for (int task = t; task < 8 * N_; task += TPB) {
            int bb0 = (task & 7) * 2, n = task >> 3;
            int idx0 = bb0 * N_ + n, idx1 = idx0 + N_;
            float pv0[10], pv1[10], av0[10], av1[10];
#pragma unroll
            for (int d = 0; d < 10; ++d) {
                pv0[d] = sm[OFF_P + d * 1120 + idx0];
                pv1[d] = sm[OFF_P + d * 1120 + idx1];
            }
            {
                const u64* xr = (const u64*)(sm + OFF_X) + n * XST_ + bb0 * 5;
#pragma unroll
                for (int s2 = 0; s2 < 5; ++s2) {
                    unpack2(xr[s2],     av0[2 * s2], av0[2 * s2 + 1]);
                    unpack2(xr[5 + s2], av1[2 * s2], av1[2 * s2 + 1]);
                }
            }
            // r gate
            u64 r0a[5], r1a[5];
#pragma unroll
            for (int s2 = 0; s2 < 5; ++s2) {
                u64 b = ((const u64*)(sm + OFF_BR2))[s2];
                r0a[s2] = b; r1a[s2] = b;
            }
            const float* WRb = sm + OFF_WR2;
#pragma unroll
            for (int j = 0; j < 20; ++j) {
                u64 o0 = pack2(j < 10 ? av0[j] : pv0[j - 10]);
                u64 o1 = pack2(j < 10 ? av1[j] : pv1[j - 10]);
                ulonglong2 wa = *(const ulonglong2*)(WRb + j * 12);
                ulonglong2 wb = *(const ulonglong2*)(WRb + j * 12 + 4);
                u64 wc = *(const u64*)(WRb + j * 12 + 8);
                r0a[0] = ffma2(o0, wa.x, r0a[0]); r1a[0] = ffma2(o1, wa.x, r1a[0]);
                r0a[1] = ffma2(o0, wa.y, r0a[1]); r1a[1] = ffma2(o1, wa.y, r1a[1]);
                r0a[2] = ffma2(o0, wb.x, r0a[2]); r1a[2] = ffma2(o1, wb.x, r1a[2]);
                r0a[3] = ffma2(o0, wb.y, r0a[3]); r1a[3] = ffma2(o1, wb.y, r1a[3]);
                r0a[4] = ffma2(o0, wc,   r0a[4]); r1a[4] = ffma2(o1, wc,   r1a[4]);
            }
            float rp0[10], rp1[10];
#pragma unroll
            for (int s2 = 0; s2 < 5; ++s2) {
                float x, y;
                unpack2(r0a[s2], x, y);
                rp0[2 * s2] = sigf(x) * pv0[2 * s2];
                rp0[2 * s2 + 1] = sigf(y) * pv0[2 * s2 + 1];
                unpack2(r1a[s2], x, y);
                rp1[2 * s2] = sigf(x) * pv1[2 * s2];
                rp1[2 * s2 + 1] = sigf(y) * pv1[2 * s2 + 1];
            }
            // z and h_hat
            u64 z0a[5], z1a[5], h0a[5], h1a[5];
#pragma unroll
            for (int s2 = 0; s2 < 5; ++s2) {
                u64 bz2 = ((const u64*)(sm + OFF_BZ2))[s2];
                u64 bh2 = ((const u64*)(sm + OFF_BH2))[s2];
                z0a[s2] = bz2; z1a[s2] = bz2;
                h0a[s2] = bh2; h1a[s2] = bh2;
            }
            const float* WZb = sm + OFF_WZ2;
            const float* WHb = sm + OFF_WH2;
#pragma unroll
            for (int j = 0; j < 20; ++j) {
                u64 o0 = pack2(j < 10 ? av0[j] : pv0[j - 10]);
                u64 o1 = pack2(j < 10 ? av1[j] : pv1[j - 10]);
                u64 q0 = (j < 10) ? o0 : pack2(rp0[j - 10]);
                u64 q1 = (j < 10) ? o1 : pack2(rp1[j - 10]);
                ulonglong2 za = *(const ulonglong2*)(WZb + j * 12);
                ulonglong2 zb = *(const ulonglong2*)(WZb + j * 12 + 4);
                u64 zc = *(const u64*)(WZb + j * 12 + 8);
                ulonglong2 ha = *(const ulonglong2*)(WHb + j * 12);
                ulonglong2 hb = *(const ulonglong2*)(WHb + j * 12 + 4);
                u64 hc = *(const u64*)(WHb + j * 12 + 8);
                z0a[0] = ffma2(o0, za.x, z0a[0]); z1a[0] = ffma2(o1, za.x, z1a[0]);
                z0a[1] = ffma2(o0, za.y, z0a[1]); z1a[1] = ffma2(o1, za.y, z1a[1]);
                z0a[2] = ffma2(o0, zb.x, z0a[2]); z1a[2] = ffma2(o1, zb.x, z1a[2]);
                z0a[3] = ffma2(o0, zb.y, z0a[3]); z1a[3] = ffma2(o1, zb.y, z1a[3]);
                z0a[4] = ffma2(o0, zc,   z0a[4]); z1a[4] = ffma2(o1, zc,   z1a[4]);
                h0a[0] = ffma2(q0, ha.x, h0a[0]); h1a[0] = ffma2(q1, ha.x, h1a[0]);
                h0a[1] = ffma2(q0, ha.y, h0a[1]); h1a[1] = ffma2(q1, ha.y, h1a[1]);
                h0a[2] = ffma2(q0, hb.x, h0a[2]); h1a[2] = ffma2(q1, hb.x, h1a[2]);
                h0a[3] = ffma2(q0, hb.y, h0a[3]); h1a[3] = ffma2(q1, hb.y, h1a[3]);
                h0a[4] = ffma2(q0, hc,   h0a[4]); h1a[4] = ffma2(q1, hc,   h1a[4]);
            }
#pragma unroll
            for (int s2 = 0; s2 < 5; ++s2) {
                float zx, zy, hx, hy;
                unpack2(z0a[s2], zx, zy);
                unpack2(h0a[s2], hx, hy);
                zx = sigf(zx); zy = sigf(zy);
                hx = tanh_(hx); hy = tanh_(hy);
                sm[OFF_P + (2 * s2) * 1120 + idx0] =
                    pv0[2 * s2] + zx * (hx - pv0[2 * s2]);
                sm[OFF_P + (2 * s2 + 1) * 1120 + idx0] =
                    pv0[2 * s2 + 1] + zy * (hy - pv0[2 * s2 + 1]);
                unpack2(z1a[s2], zx, zy);
                unpack2(h1a[s2], hx, hy);
                zx = sigf(zx); zy = sigf(zy);
                hx = tanh_(hx); hy = tanh_(hy);
                sm[OFF_P + (2 * s2) * 1120 + idx1] =
                    pv1[2 * s2] + zx * (hx - pv1[2 * s2]);
                sm[OFF_P + (2 * s2 + 1) * 1120 + idx1] =
                    pv1[2 * s2 + 1] + zy * (hy - pv1[2 * s2 + 1]);
            }
        }
        __syncthreads();
    }

    // ---- output ----
#pragma unroll 1
    for (int task = t; task < BB_ * N_; task += TPB) {
        int bb = task / N_, n = task - bb * N_;
        int idx = bb * N_ + n;
        float an = annotation[b0i * N_ + idx];
        float o = sm[OFF_BO2];
#pragma unroll 2
        for (int s = 0; s < 10; ++s) {
            float a0 = sm[OFF_BO1 + s];
#pragma unroll
            for (int j = 0; j < 10; ++j)
                a0 += sm[OFF_P + j * 1120 + idx] * sm[OFF_WO1 + s * 11 + j];
            a0 += an * sm[OFF_WO1 + s * 11 + 10];
            o += tanh_(a0) * sm[OFF_WO2 + s];
        }
        out[b0i * N_ + idx] = o;
    }
}

extern "C" void kernel_launch(void* const* d_in, const int* in_sizes, int n_in,
                              void* d_out, int out_size) {
    const float* annotation = (const float*)d_in[0];
    const float* A    = (const float*)d_in[1];
    const float* W_in = (const float*)d_in[2];
    const float* b_in = (const float*)d_in[3];
    const float* Wr   = (const float*)d_in[4];
    const float* br   = (const float*)d_in[5];
    const float* Wz   = (const float*)d_in[6];
    const float* bz   = (const float*)d_in[7];
    const float* Wh   = (const float*)d_in[8];
    const float* bh   = (const float*)d_in[9];
    const float* Wo1  = (const float*)d_in[10];
    const float* bo1  = (const float*)d_in[11];
    const float* Wo2  = (const float*)d_in[12];
    const float* bo2  = (const float*)d_in[13];
    float* out = (float*)d_out;

    const int smem_bytes = SMEM_FLOATS * (int)sizeof(float);
    cudaFuncSetAttribute(ggnn_kernel,
                         cudaFuncAttributeMaxDynamicSharedMemorySize, smem_bytes);
    ggnn_kernel<<<B_ / BB_, TPB, smem_bytes>>>(
        annotation, A, W_in, b_in, Wr, br, Wz, bz, Wh, bh,
        Wo1, bo1, Wo2, bo2, out);
}

// round 13
// speedup vs baseline: 1.0600x; 1.0600x over previous
#include <cuda_runtime.h>

#define TPB 256

constexpr int B_     = 16384;
constexpr int N_     = 70;
constexpr int E_     = 3;
constexpr int S_     = 10;
constexpr int STEPS_ = 5;
constexpr int BB_    = 16;            // batch elements per CTA
constexpr int XST_   = 82;            // X row stride in u64 (padded; 80 used)

// ---- shared memory layout (float offsets) ----
constexpr int OFF_X    = 0;                      // 70*82 u64 = 11480 fl
constexpr int OFF_P    = 11480;                  // 10 planes * 1120 = 11200
constexpr int OFF_AS   = 22680;                  // full e-slice: 70*70 = 4900
constexpr int OFF_WIN2 = 27580;                  // [e][d][6] f2 = 360
constexpr int OFF_BIN2 = 27940;                  // 30 (+2 pad)
constexpr int OFF_WR2  = 27972;                  // [j][6] f2 = 240
constexpr int OFF_BR2  = 28212;                  // 10 (+2 pad)
constexpr int OFF_WZ2  = 28224;                  // 240
constexpr int OFF_BZ2  = 28464;                  // 10 (+2 pad)
constexpr int OFF_WH2  = 28476;                  // 240
constexpr int OFF_BH2  = 28716;                  // 10
constexpr int OFF_WO1  = 28726;                  // 110
constexpr int OFF_BO1  = 28836;                  // 10
constexpr int OFF_WO2  = 28846;                  // 10
constexpr int OFF_BO2  = 28856;                  // 1
constexpr int SMEM_FLOATS = 28857;               // 115428 B/CTA -> 2 CTAs/SM

typedef unsigned long long u64;

__device__ __forceinline__ u64 ffma2(u64 a, u64 b, u64 c) {
    u64 d;
    asm("fma.rn.f32x2 %0, %1, %2, %3;" : "=l"(d) : "l"(a), "l"(b), "l"(c));
    return d;
}
__device__ __forceinline__ u64 pack2(float x) {
    u64 d;
    asm("mov.b64 %0, {%1, %1};" : "=l"(d) : "f"(x));
    return d;
}
__device__ __forceinline__ void unpack2(u64 v, float& x, float& y) {
    asm("mov.b64 {%0, %1}, %2;" : "=f"(x), "=f"(y) : "l"(v));
}

__device__ __forceinline__ float sigf(float x) {
    return __fdividef(1.0f, 1.0f + __expf(-x));
}
__device__ __forceinline__ float tanh_(float x) {
    float e = __expf(-2.0f * x);
    return __fdividef(1.0f - e, 1.0f + e);
}

extern __shared__ float sm[];

// ---- stage A[:, e*70 : (e+1)*70] into SMEM (contiguous 70x70) ----
__device__ __forceinline__ void stageA(const float* __restrict__ Ag, int e,
                                       int t) {
#pragma unroll 1
    for (int i = t; i < 70 * 70; i += TPB) {
        int row = i / 70, kk = i - row * 70;
        sm[OFF_AS + i] = Ag[row * 210 + e * 70 + kk];
    }
}

// ---- load both X rows (even/odd k) for one k2 into a 10-u64 buffer ----
// tx is warp-uniform-pair (t>>4): loads are 16-way broadcast, 1-2 wavefronts.
__device__ __forceinline__ void loadX(u64 (&b)[10], const u64* xE, int tx) {
    const u64* xO = xE + XST_;
    ulonglong2 p;
    p = *(const ulonglong2*)(xE + 4 * tx);     b[0] = p.x; b[1] = p.y;
    p = *(const ulonglong2*)(xE + 4 * tx + 2); b[2] = p.x; b[3] = p.y;
    b[4] = xE[64 + tx];
    p = *(const ulonglong2*)(xO + 4 * tx);     b[5] = p.x; b[6] = p.y;
    p = *(const ulonglong2*)(xO + 4 * tx + 2); b[7] = p.x; b[8] = p.y;
    b[9] = xO[64 + tx];
}

// ---- one k2 of FFMA2 work against a preloaded X buffer (5 uniform rows) ----
// Rows >= 70 (i=4, ty>=6) read in-bounds-of-smem garbage; acc row unused.
__device__ __forceinline__ void computeK(u64 (&acc)[5][5], const u64 (&b)[10],
                                         const u64* A64, int rbase, int k2) {
#pragma unroll
    for (int i = 0; i < 5; ++i) {
        u64 a2 = A64[rbase + i * 560 + k2];
        float lo, hi;
        unpack2(a2, lo, hi);
        u64 pE = pack2(lo);
        acc[i][0] = ffma2(pE, b[0], acc[i][0]);
        acc[i][1] = ffma2(pE, b[1], acc[i][1]);
        acc[i][2] = ffma2(pE, b[2], acc[i][2]);
        acc[i][3] = ffma2(pE, b[3], acc[i][3]);
        acc[i][4] = ffma2(pE, b[4], acc[i][4]);
        u64 pO = pack2(hi);
        acc[i][0] = ffma2(pO, b[5], acc[i][0]);
        acc[i][1] = ffma2(pO, b[6], acc[i][1]);
        acc[i][2] = ffma2(pO, b[7], acc[i][2]);
        acc[i][3] = ffma2(pO, b[8], acc[i][3]);
        acc[i][4] = ffma2(pO, b[9], acc[i][4]);
    }
}

// ---- full-e GEMM, X software-pipelined (2-deep ping-pong), R11 mapping ----
__device__ __forceinline__ void gemm_full(u64 (&acc)[5][5], const u64* Xb,
                                          int tx, int ty) {
    const u64* A64 = (const u64*)(sm + OFF_AS);
    const int rbase = ty * 35;
    u64 b0[10], b1[10];
    loadX(b0, Xb, tx);
#pragma unroll 1
    for (int k2 = 0; k2 < 34; k2 += 2) {
        loadX(b1, Xb + (2 * (k2 + 1)) * XST_, tx);
        computeK(acc, b0, A64, rbase, k2);
        loadX(b0, Xb + (2 * (k2 + 2)) * XST_, tx);
        computeK(acc, b1, A64, rbase, k2 + 1);
    }
    computeK(acc, b0, A64, rbase, 34);
}

__global__ void __launch_bounds__(TPB, 2) ggnn_kernel(
    const float* __restrict__ annotation, const float* __restrict__ Ag,
    const float* __restrict__ W_in, const float* __restrict__ b_in,
    const float* __restrict__ Wr, const float* __restrict__ br,
    const float* __restrict__ Wz, const float* __restrict__ bz,
    const float* __restrict__ Wh, const float* __restrict__ bh,
    const float* __restrict__ Wo1, const float* __restrict__ bo1,
    const float* __restrict__ Wo2, const float* __restrict__ bo2,
    float* __restrict__ out)
{
    const int t  = threadIdx.x;
    const int b0 = blockIdx.x * BB_;

    // ---- stage paired weight tables ----
    for (int i = t; i < 150; i += TPB) {      // WIN2 [e][d][6]
        int s2 = i % 5, d = (i / 5) % 10, e = i / 50;
        ((float2*)(sm + OFF_WIN2))[e * 60 + d * 6 + s2] =
            make_float2(W_in[(e * 10 + 2 * s2) * 10 + d],
                        W_in[(e * 10 + 2 * s2 + 1) * 10 + d]);
    }
    if (t < 15) {                             // BIN2 [e][s2]
        int s2 = t % 5, e = t / 5;
        ((float2*)(sm + OFF_BIN2))[t] =
            make_float2(b_in[e * 10 + 2 * s2], b_in[e * 10 + 2 * s2 + 1]);
    }
    for (int i = t; i < 100; i += TPB) {      // W{r,z,h}2 [j][6]
        int s2 = i % 5, j = i / 5;
        ((float2*)(sm + OFF_WR2))[j * 6 + s2] =
            make_float2(Wr[2 * s2 * 20 + j], Wr[(2 * s2 + 1) * 20 + j]);
        ((float2*)(sm + OFF_WZ2))[j * 6 + s2] =
            make_float2(Wz[2 * s2 * 20 + j], Wz[(2 * s2 + 1) * 20 + j]);
        ((float2*)(sm + OFF_WH2))[j * 6 + s2] =
            make_float2(Wh[2 * s2 * 20 + j], Wh[(2 * s2 + 1) * 20 + j]);
    }
    if (t < 5) {
        ((float2*)(sm + OFF_BR2))[t] = make_float2(br[2 * t], br[2 * t + 1]);
        ((float2*)(sm + OFF_BZ2))[t] = make_float2(bz[2 * t], bz[2 * t + 1]);
        ((float2*)(sm + OFF_BH2))[t] = make_float2(bh[2 * t], bh[2 * t + 1]);
    }
    for (int i = t; i < 110; i += TPB) sm[OFF_WO1 + i] = Wo1[i];
    if (t < 10) { sm[OFF_BO1 + t] = bo1[t]; sm[OFF_WO2 + t] = Wo2[t]; }
    if (t == 0) sm[OFF_BO2] = bo2[0];

    // ---- prop init: P[0][idx] = ann, P[1..9][idx] = 0 ----
    for (int i = t; i < BB_ * N_; i += TPB) {
        float a = annotation[b0 * N_ + i];
        sm[OFF_P + i] = a;
#pragma unroll
        for (int d = 1; d < S_; ++d) sm[OFF_P + d * 1120 + i] = 0.0f;
    }
    __syncthreads();

    const int tx = t >> 4;   // column group (0..15) — warp-uniform pair
    const int ty = t & 15;   // row group (0..15)    — warp-varying

    u64 acc[5][5];

#pragma unroll 1
    for (int step = 0; step < STEPS_; ++step) {
#pragma unroll
        for (int i = 0; i < 5; ++i)
#pragma unroll
            for (int j = 0; j < 5; ++j) acc[i][j] = 0ull;

#pragma unroll 1
        for (int e = 0; e < 3; ++e) {
            // ---- stage full A slice + build X (disjoint writes, one phase) --
            stageA(Ag, e, t);
#pragma unroll 1
            for (int task = t; task < BB_ * N_; task += TPB) {
                int bb = task & 15, n = task >> 4;
                int idx = bb * N_ + n;
                const u64* B2 = (const u64*)(sm + OFF_BIN2) + e * 5;
                u64 a0 = B2[0], a1 = B2[1], a2 = B2[2], a3 = B2[3], a4 = B2[4];
                const float* Wb = sm + OFF_WIN2 + e * 120;
#pragma unroll
                for (int d = 0; d < 10; ++d) {
                    u64 p2 = pack2(sm[OFF_P + d * 1120 + idx]);
                    ulonglong2 wa = *(const ulonglong2*)(Wb + d * 12);
                    ulonglong2 wb = *(const ulonglong2*)(Wb + d * 12 + 4);
                    u64 wc = *(const u64*)(Wb + d * 12 + 8);
                    a0 = ffma2(p2, wa.x, a0);
                    a1 = ffma2(p2, wa.y, a1);
                    a2 = ffma2(p2, wb.x, a2);
                    a3 = ffma2(p2, wb.y, a3);
                    a4 = ffma2(p2, wc, a4);
                }
                u64* xo = (u64*)(sm + OFF_X) + n * XST_ + bb * 5;
                xo[0] = a0; xo[1] = a1; xo[2] = a2; xo[3] = a3; xo[4] = a4;
            }
            __syncthreads();

            gemm_full(acc, (const u64*)(sm + OFF_X), tx, ty);
            __syncthreads();
        }

        // ---- write a_in back into X (rows < 70 only) ----
        {
            u64* X64 = (u64*)(sm + OFF_X);
#pragma unroll
            for (int i = 0; i < 4; ++i) {
                u64* xo = X64 + (ty + 16 * i) * XST_;
                ulonglong2 v0; v0.x = acc[i][0]; v0.y = acc[i][1];
                ulonglong2 v1; v1.x = acc[i][2]; v1.y = acc[i][3];
                *(ulonglong2*)(xo + 4 * tx) = v0;
                *(ulonglong2*)(xo + 4 * tx + 2) = v1;
                xo[64 + tx] = acc[i][4];
            }
            if (ty < 6) {
                u64* xo = X64 + (64 + ty) * XST_;
                ulonglong2 v0; v0.x = acc[4][0]; v0.y = acc[4][1];
                ulonglong2 v1; v1.x = acc[4][2]; v1.y = acc[4][3];
                *(ulonglong2*)(xo + 4 * tx) = v0;
                *(ulonglong2*)(xo + 4 * tx + 2) = v1;
                xo[64 + tx] = acc[4][4];
            }
        }
        __syncthreads();

        // ---- gates: 2 batch elements per task ----
#pragma unroll 1
        for (int task = t; task < 8 * N_; task += TPB) {
            int bb0 = (task & 7) * 2, n = task >> 3;
            int idx0 = bb0 * N_ + n, idx1 = idx0 + N_;
            float pv0[10], pv1[10], av0[10], av1[10];
#pragma unroll
            for (int d = 0; d < 10; ++d) {
                pv0[d] = sm[OFF_P + d * 1120 + idx0];
                pv1[d] = sm[OFF_P + d * 1120 + idx1];
            }
            {
                const u64* xr = (const u64*)(sm + OFF_X) + n * XST_ + bb0 * 5;
#pragma unroll
                for (int s2 = 0; s2 < 5; ++s2) {
                    unpack2(xr[s2],     av0[2 * s2], av0[2 * s2 + 1]);
                    unpack2(xr[5 + s2], av1[2 * s2], av1[2 * s2 + 1]);
                }
            }
            // r gate
            u64 r0a[5], r1a[5];
#pragma unroll
            for (int s2 = 0; s2 < 5; ++s2) {
                u64 b = ((const u64*)(sm + OFF_BR2))[s2];
                r0a[s2] = b; r1a[s2] = b;
            }
            const float* WRb = sm + OFF_WR2;
#pragma unroll
            for (int j = 0; j < 20; ++j) {
                u64 o0 = pack2(j < 10 ? av0[j] : pv0[j - 10]);
                u64 o1 = pack2(j < 10 ? av1[j] : pv1[j - 10]);
                ulonglong2 wa = *(const ulonglong2*)(WRb + j * 12);
                ulonglong2 wb = *(const ulonglong2*)(WRb + j * 12 + 4);
                u64 wc = *(const u64*)(WRb + j * 12 + 8);
                r0a[0] = ffma2(o0, wa.x, r0a[0]); r1a[0] = ffma2(o1, wa.x, r1a[0]);
                r0a[1] = ffma2(o0, wa.y, r0a[1]); r1a[1] = ffma2(o1, wa.y, r1a[1]);
                r0a[2] = ffma2(o0, wb.x, r0a[2]); r1a[2] = ffma2(o1, wb.x, r1a[2]);
                r0a[3] = ffma2(o0, wb.y, r0a[3]); r1a[3] = ffma2(o1, wb.y, r1a[3]);
                r0a[4] = ffma2(o0, wc,   r0a[4]); r1a[4] = ffma2(o1, wc,   r1a[4]);
            }
            float rp0[10], rp1[10];
#pragma unroll
            for (int s2 = 0; s2 < 5; ++s2) {
                float x, y;
                unpack2(r0a[s2], x, y);
                rp0[2 * s2] = sigf(x) * pv0[2 * s2];
                rp0[2 * s2 + 1] = sigf(y) * pv0[2 * s2 + 1];
                unpack2(r1a[s2], x, y);
                rp1[2 * s2] = sigf(x) * pv1[2 * s2];
                rp1[2 * s2 + 1] = sigf(y) * pv1[2 * s2 + 1];
            }
            // z and h_hat
            u64 z0a[5], z1a[5], h0a[5], h1a[5];
#pragma unroll
            for (int s2 = 0; s2 < 5; ++s2) {
                u64 bz2 = ((const u64*)(sm + OFF_BZ2))[s2];
                u64 bh2 = ((const u64*)(sm + OFF_BH2))[s2];
                z0a[s2] = bz2; z1a[s2] = bz2;
                h0a[s2] = bh2; h1a[s2] = bh2;
            }
            const float* WZb = sm + OFF_WZ2;
            const float* WHb = sm + OFF_WH2;
#pragma unroll
            for (int j = 0; j < 20; ++j) {
                u64 o0 = pack2(j < 10 ? av0[j] : pv0[j - 10]);
                u64 o1 = pack2(j < 10 ? av1[j] : pv1[j - 10]);
                u64 q0 = (j < 10) ? o0 : pack2(rp0[j - 10]);
                u64 q1 = (j < 10) ? o1 : pack2(rp1[j - 10]);
                ulonglong2 za = *(const ulonglong2*)(WZb + j * 12);
                ulonglong2 zb = *(const ulonglong2*)(WZb + j * 12 + 4);
                u64 zc = *(const u64*)(WZb + j * 12 + 8);
                ulonglong2 ha = *(const ulonglong2*)(WHb + j * 12);
                ulonglong2 hb = *(const ulonglong2*)(WHb + j * 12 + 4);
                u64 hc = *(const u64*)(WHb + j * 12 + 8);
                z0a[0] = ffma2(o0, za.x, z0a[0]); z1a[0] = ffma2(o1, za.x, z1a[0]);
                z0a[1] = ffma2(o0, za.y, z0a[1]); z1a[1] = ffma2(o1, za.y, z1a[1]);
                z0a[2] = ffma2(o0, zb.x, z0a[2]); z1a[2] = ffma2(o1, zb.x, z1a[2]);
                z0a[3] = ffma2(o0, zb.y, z0a[3]); z1a[3] = ffma2(o1, zb.y, z1a[3]);
                z0a[4] = ffma2(o0, zc,   z0a[4]); z1a[4] = ffma2(o1, zc,   z1a[4]);
                h0a[0] = ffma2(q0, ha.x, h0a[0]); h1a[0] = ffma2(q1, ha.x, h1a[0]);
                h0a[1] = ffma2(q0, ha.y, h0a[1]); h1a[1] = ffma2(q1, ha.y, h1a[1]);
                h0a[2] = ffma2(q0, hb.x, h0a[2]); h1a[2] = ffma2(q1, hb.x, h1a[2]);
                h0a[3] = ffma2(q0, hb.y, h0a[3]); h1a[3] = ffma2(q1, hb.y, h1a[3]);
                h0a[4] = ffma2(q0, hc,   h0a[4]); h1a[4] = ffma2(q1, hc,   h1a[4]);
            }
#pragma unroll
            for (int s2 = 0; s2 < 5; ++s2) {
                float zx, zy, hx, hy;
                unpack2(z0a[s2], zx, zy);
                unpack2(h0a[s2], hx, hy);
                zx = sigf(zx); zy = sigf(zy);
                hx = tanh_(hx); hy = tanh_(hy);
                sm[OFF_P + (2 * s2) * 1120 + idx0] =
                    pv0[2 * s2] + zx * (hx - pv0[2 * s2]);
                sm[OFF_P + (2 * s2 + 1) * 1120 + idx0] =
                    pv0[2 * s2 + 1] + zy * (hy - pv0[2 * s2 + 1]);
                unpack2(z1a[s2], zx, zy);
                unpack2(h1a[s2], hx, hy);
                zx = sigf(zx); zy = sigf(zy);
                hx = tanh_(hx); hy = tanh_(hy);
                sm[OFF_P + (2 * s2) * 1120 + idx1] =
                    pv1[2 * s2] + zx * (hx - pv1[2 * s2]);
                sm[OFF_P + (2 * s2 + 1) * 1120 + idx1] =
                    pv1[2 * s2 + 1] + zy * (hy - pv1[2 * s2 + 1]);
            }
        }
        __syncthreads();
    }

    // ---- output ----
#pragma unroll 1
    for (int task = t; task < BB_ * N_; task += TPB) {
        int bb = task / N_, n = task - bb * N_;
        int idx = bb * N_ + n;
        float an = annotation[b0 * N_ + idx];
        float o = sm[OFF_BO2];
#pragma unroll 2
        for (int s = 0; s < 10; ++s) {
            float a0 = sm[OFF_BO1 + s];
#pragma unroll
            for (int j = 0; j < 10; ++j)
                a0 += sm[OFF_P + j * 1120 + idx] * sm[OFF_WO1 + s * 11 + j];
            a0 += an * sm[OFF_WO1 + s * 11 + 10];
            o += tanh_(a0) * sm[OFF_WO2 + s];
        }
        out[b0 * N_ + idx] = o;
    }
}

extern "C" void kernel_launch(void* const* d_in, const int* in_sizes, int n_in,
                              void* d_out, int out_size) {
    const float* annotation = (const float*)d_in[0];
    const float* A    = (const float*)d_in[1];
    const float* W_in = (const float*)d_in[2];
    const float* b_in = (const float*)d_in[3];
    const float* Wr   = (const float*)d_in[4];
    const float* br   = (const float*)d_in[5];
    const float* Wz   = (const float*)d_in[6];
    const float* bz   = (const float*)d_in[7];
    const float* Wh   = (const float*)d_in[8];
    const float* bh   = (const float*)d_in[9];
    const float* Wo1  = (const float*)d_in[10];
    const float* bo1  = (const float*)d_in[11];
    const float* Wo2  = (const float*)d_in[12];
    const float* bo2  = (const float*)d_in[13];
    float* out = (float*)d_out;

    const int smem_bytes = SMEM_FLOATS * (int)sizeof(float);
    cudaFuncSetAttribute(ggnn_kernel,
                         cudaFuncAttributeMaxDynamicSharedMemorySize, smem_bytes);
    ggnn_kernel<<<B_ / BB_, TPB, smem_bytes>>>(
        annotation, A, W_in, b_in, Wr, br, Wz, bz, Wh, bh,
        Wo1, bo1, Wo2, bo2, out);
}

// round 14
// speedup vs baseline: 1.1201x; 1.0567x over previous
#include <cuda_runtime.h>

#define TPB 256

constexpr int B_     = 16384;
constexpr int N_     = 70;
constexpr int E_     = 3;
constexpr int S_     = 10;
constexpr int STEPS_ = 5;
constexpr int BB_    = 16;            // batch elements per CTA
constexpr int XST_   = 82;            // X row stride in u64 (padded; 80 used)

// ---- shared memory layout (float offsets) ----
constexpr int OFF_X    = 0;                      // 70*82 u64 = 11480 fl
constexpr int OFF_P    = 11480;                  // 10 planes * 1120 = 11200
constexpr int OFF_AS   = 22680;                  // full e-slice: 70*70 = 4900
constexpr int OFF_WIN2 = 27580;                  // [e][d][6] f2 = 360
constexpr int OFF_BIN2 = 27940;                  // 30 (+2 pad)
constexpr int OFF_WR2  = 27972;                  // [j][6] f2 = 240
constexpr int OFF_BR2  = 28212;                  // 10 (+2 pad)
constexpr int OFF_WZ2  = 28224;                  // 240
constexpr int OFF_BZ2  = 28464;                  // 10 (+2 pad)
constexpr int OFF_WH2  = 28476;                  // 240
constexpr int OFF_BH2  = 28716;                  // 10
constexpr int OFF_WO1  = 28726;                  // 110
constexpr int OFF_BO1  = 28836;                  // 10
constexpr int OFF_WO2  = 28846;                  // 10
constexpr int OFF_BO2  = 28856;                  // 1
constexpr int SMEM_FLOATS = 28857;               // 115428 B/CTA -> 2 CTAs/SM

typedef unsigned long long u64;

__device__ __forceinline__ u64 ffma2(u64 a, u64 b, u64 c) {
    u64 d;
    asm("fma.rn.f32x2 %0, %1, %2, %3;" : "=l"(d) : "l"(a), "l"(b), "l"(c));
    return d;
}
__device__ __forceinline__ u64 pack2(float x) {
    u64 d;
    asm("mov.b64 %0, {%1, %1};" : "=l"(d) : "f"(x));
    return d;
}
__device__ __forceinline__ void unpack2(u64 v, float& x, float& y) {
    asm("mov.b64 {%0, %1}, %2;" : "=f"(x), "=f"(y) : "l"(v));
}

// hardware tanh (sm_75+): 1 MUFU op, rel err ~2^-11
__device__ __forceinline__ float tanh_(float x) {
    float y;
    asm("tanh.approx.f32 %0, %1;" : "=f"(y) : "f"(x));
    return y;
}
// sigmoid via tanh: sig(x) = 0.5 + 0.5*tanh(x/2)
__device__ __forceinline__ float sigf(float x) {
    return fmaf(0.5f, tanh_(0.5f * x), 0.5f);
}

extern __shared__ float sm[];

// ---- stage A[:, e*70 : (e+1)*70] into SMEM (contiguous 70x70) ----
__device__ __forceinline__ void stageA(const float* __restrict__ Ag, int e,
                                       int t) {
#pragma unroll 1
    for (int i = t; i < 70 * 70; i += TPB) {
        int row = i / 70, kk = i - row * 70;
        sm[OFF_AS + i] = Ag[row * 210 + e * 70 + kk];
    }
}

// ---- GEMM full e: rows ty+16i (i=0..4), cols {4tx..4tx+3, 64+tx} ----
// X loads broadcast; A via LDS.64 spanning 2 k (row stride 35 u64, conflict-free).
// Rows >= 70 (i=4, ty>=6) read in-bounds garbage; their acc row is never used.
__device__ __forceinline__ void gemm_full(u64 (&acc)[5][5], const u64* Xb,
                                          int tx, int ty) {
    const u64* A64 = (const u64*)(sm + OFF_AS);
    const int rbase = ty * 35;
#pragma unroll 1
    for (int k2 = 0; k2 < 35; ++k2) {
        const u64* xE = Xb + (2 * k2) * XST_;
        const u64* xO = xE + XST_;
        ulonglong2 eA = *(const ulonglong2*)(xE + 4 * tx);
        ulonglong2 eB = *(const ulonglong2*)(xE + 4 * tx + 2);
        u64 eC = xE[64 + tx];
        ulonglong2 oA = *(const ulonglong2*)(xO + 4 * tx);
        ulonglong2 oB = *(const ulonglong2*)(xO + 4 * tx + 2);
        u64 oC = xO[64 + tx];
#pragma unroll
        for (int i = 0; i < 5; ++i) {
            u64 a2 = A64[rbase + i * 560 + k2];
            float lo, hi;
            unpack2(a2, lo, hi);
            u64 pE = pack2(lo);
            acc[i][0] = ffma2(pE, eA.x, acc[i][0]);
            acc[i][1] = ffma2(pE, eA.y, acc[i][1]);
            acc[i][2] = ffma2(pE, eB.x, acc[i][2]);
            acc[i][3] = ffma2(pE, eB.y, acc[i][3]);
            acc[i][4] = ffma2(pE, eC,   acc[i][4]);
            u64 pO = pack2(hi);
            acc[i][0] = ffma2(pO, oA.x, acc[i][0]);
            acc[i][1] = ffma2(pO, oA.y, acc[i][1]);
            acc[i][2] = ffma2(pO, oB.x, acc[i][2]);
            acc[i][3] = ffma2(pO, oB.y, acc[i][3]);
            acc[i][4] = ffma2(pO, oC,   acc[i][4]);
        }
    }
}

__global__ void __launch_bounds__(TPB, 2) ggnn_kernel(
    const float* __restrict__ annotation, const float* __restrict__ Ag,
    const float* __restrict__ W_in, const float* __restrict__ b_in,
    const float* __restrict__ Wr, const float* __restrict__ br,
    const float* __restrict__ Wz, const float* __restrict__ bz,
    const float* __restrict__ Wh, const float* __restrict__ bh,
    const float* __restrict__ Wo1, const float* __restrict__ bo1,
    const float* __restrict__ Wo2, const float* __restrict__ bo2,
    float* __restrict__ out)
{
    const int t  = threadIdx.x;
    const int b0 = blockIdx.x * BB_;

    // ---- stage paired weight tables ----
    for (int i = t; i < 150; i += TPB) {      // WIN2 [e][d][6]
        int s2 = i % 5, d = (i / 5) % 10, e = i / 50;
        ((float2*)(sm + OFF_WIN2))[e * 60 + d * 6 + s2] =
            make_float2(W_in[(e * 10 + 2 * s2) * 10 + d],
                        W_in[(e * 10 + 2 * s2 + 1) * 10 + d]);
    }
    if (t < 15) {                             // BIN2 [e][s2]
        int s2 = t % 5, e = t / 5;
        ((float2*)(sm + OFF_BIN2))[t] =
            make_float2(b_in[e * 10 + 2 * s2], b_in[e * 10 + 2 * s2 + 1]);
    }
    for (int i = t; i < 100; i += TPB) {      // W{r,z,h}2 [j][6]
        int s2 = i % 5, j = i / 5;
        ((float2*)(sm + OFF_WR2))[j * 6 + s2] =
            make_float2(Wr[2 * s2 * 20 + j], Wr[(2 * s2 + 1) * 20 + j]);
        ((float2*)(sm + OFF_WZ2))[j * 6 + s2] =
            make_float2(Wz[2 * s2 * 20 + j], Wz[(2 * s2 + 1) * 20 + j]);
        ((float2*)(sm + OFF_WH2))[j * 6 + s2] =
            make_float2(Wh[2 * s2 * 20 + j], Wh[(2 * s2 + 1) * 20 + j]);
    }
    if (t < 5) {
        ((float2*)(sm + OFF_BR2))[t] = make_float2(br[2 * t], br[2 * t + 1]);
        ((float2*)(sm + OFF_BZ2))[t] = make_float2(bz[2 * t], bz[2 * t + 1]);
        ((float2*)(sm + OFF_BH2))[t] = make_float2(bh[2 * t], bh[2 * t + 1]);
    }
    for (int i = t; i < 110; i += TPB) sm[OFF_WO1 + i] = Wo1[i];
    if (t < 10) { sm[OFF_BO1 + t] = bo1[t]; sm[OFF_WO2 + t] = Wo2[t]; }
    if (t == 0) sm[OFF_BO2] = bo2[0];

    // ---- prop init: P[0][idx] = ann, P[1..9][idx] = 0 ----
    for (int i = t; i < BB_ * N_; i += TPB) {
        float a = annotation[b0 * N_ + i];
        sm[OFF_P + i] = a;
#pragma unroll
        for (int d = 1; d < S_; ++d) sm[OFF_P + d * 1120 + i] = 0.0f;
    }
    __syncthreads();

    const int tx = t >> 4;   // column group (0..15) — warp-uniform pair
    const int ty = t & 15;   // row group (0..15)    — warp-varying

    u64 acc[5][5];

#pragma unroll 1
    for (int step = 0; step < STEPS_; ++step) {
#pragma unroll
        for (int i = 0; i < 5; ++i)
#pragma unroll
            for (int j = 0; j < 5; ++j) acc[i][j] = 0ull;

#pragma unroll 1
        for (int e = 0; e < 3; ++e) {
            // ---- stage full A slice + build X (disjoint writes, one phase) --
            stageA(Ag, e, t);
#pragma unroll 1
            for (int task = t; task < BB_ * N_; task += TPB) {
                int bb = task & 15, n = task >> 4;
                int idx = bb * N_ + n;
                const u64* B2 = (const u64*)(sm + OFF_BIN2) + e * 5;
                u64 a0 = B2[0], a1 = B2[1], a2 = B2[2], a3 = B2[3], a4 = B2[4];
                const float* Wb = sm + OFF_WIN2 + e * 120;
#pragma unroll
                for (int d = 0; d < 10; ++d) {
                    u64 p2 = pack2(sm[OFF_P + d * 1120 + idx]);
                    ulonglong2 wa = *(const ulonglong2*)(Wb + d * 12);
                    ulonglong2 wb = *(const ulonglong2*)(Wb + d * 12 + 4);
                    u64 wc = *(const u64*)(Wb + d * 12 + 8);
                    a0 = ffma2(p2, wa.x, a0);
                    a1 = ffma2(p2, wa.y, a1);
                    a2 = ffma2(p2, wb.x, a2);
                    a3 = ffma2(p2, wb.y, a3);
                    a4 = ffma2(p2, wc, a4);
                }
                u64* xo = (u64*)(sm + OFF_X) + n * XST_ + bb * 5;
                xo[0] = a0; xo[1] = a1; xo[2] = a2; xo[3] = a3; xo[4] = a4;
            }
            __syncthreads();

            gemm_full(acc, (const u64*)(sm + OFF_X), tx, ty);
            __syncthreads();
        }

        // ---- write a_in back into X (rows < 70 only) ----
        {
            u64* X64 = (u64*)(sm + OFF_X);
#pragma unroll
            for (int i = 0; i < 4; ++i) {
                u64* xo = X64 + (ty + 16 * i) * XST_;
                ulonglong2 v0; v0.x = acc[i][0]; v0.y = acc[i][1];
                ulonglong2 v1; v1.x = acc[i][2]; v1.y = acc[i][3];
                *(ulonglong2*)(xo + 4 * tx) = v0;
                *(ulonglong2*)(xo + 4 * tx + 2) = v1;
                xo[64 + tx] = acc[i][4];
            }
            if (ty < 6) {
                u64* xo = X64 + (64 + ty) * XST_;
                ulonglong2 v0; v0.x = acc[4][0]; v0.y = acc[4][1];
                ulonglong2 v1; v1.x = acc[4][2]; v1.y = acc[4][3];
                *(ulonglong2*)(xo + 4 * tx) = v0;
                *(ulonglong2*)(xo + 4 * tx + 2) = v1;
                xo[64 + tx] = acc[4][4];
            }
        }
        __syncthreads();

        // ---- gates: 2 batch elements per task ----
#pragma unroll 1
        for (int task = t; task < 8 * N_; task += TPB) {
            int bb0 = (task & 7) * 2, n = task >> 3;
            int idx0 = bb0 * N_ + n, idx1 = idx0 + N_;
            float pv0[10], pv1[10], av0[10], av1[10];
#pragma unroll
            for (int d = 0; d < 10; ++d) {
                pv0[d] = sm[OFF_P + d * 1120 + idx0];
                pv1[d] = sm[OFF_P + d * 1120 + idx1];
            }
            {
                const u64* xr = (const u64*)(sm + OFF_X) + n * XST_ + bb0 * 5;
#pragma unroll
                for (int s2 = 0; s2 < 5; ++s2) {
                    unpack2(xr[s2],     av0[2 * s2], av0[2 * s2 + 1]);
                    unpack2(xr[5 + s2], av1[2 * s2], av1[2 * s2 + 1]);
                }
            }
            // r gate
            u64 r0a[5], r1a[5];
#pragma unroll
            for (int s2 = 0; s2 < 5; ++s2) {
                u64 b = ((const u64*)(sm + OFF_BR2))[s2];
                r0a[s2] = b; r1a[s2] = b;
            }
            const float* WRb = sm + OFF_WR2;
#pragma unroll
            for (int j = 0; j < 20; ++j) {
                u64 o0 = pack2(j < 10 ? av0[j] : pv0[j - 10]);
                u64 o1 = pack2(j < 10 ? av1[j] : pv1[j - 10]);
                ulonglong2 wa = *(const ulonglong2*)(WRb + j * 12);
                ulonglong2 wb = *(const ulonglong2*)(WRb + j * 12 + 4);
                u64 wc = *(const u64*)(WRb + j * 12 + 8);
                r0a[0] = ffma2(o0, wa.x, r0a[0]); r1a[0] = ffma2(o1, wa.x, r1a[0]);
                r0a[1] = ffma2(o0, wa.y, r0a[1]); r1a[1] = ffma2(o1, wa.y, r1a[1]);
                r0a[2] = ffma2(o0, wb.x, r0a[2]); r1a[2] = ffma2(o1, wb.x, r1a[2]);
                r0a[3] = ffma2(o0, wb.y, r0a[3]); r1a[3] = ffma2(o1, wb.y, r1a[3]);
                r0a[4] = ffma2(o0, wc,   r0a[4]); r1a[4] = ffma2(o1, wc,   r1a[4]);
            }
            float rp0[10], rp1[10];
#pragma unroll
            for (int s2 = 0; s2 < 5; ++s2) {
                float x, y;
                unpack2(r0a[s2], x, y);
                rp0[2 * s2] = sigf(x) * pv0[2 * s2];
                rp0[2 * s2 + 1] = sigf(y) * pv0[2 * s2 + 1];
                unpack2(r1a[s2], x, y);
                rp1[2 * s2] = sigf(x) * pv1[2 * s2];
                rp1[2 * s2 + 1] = sigf(y) * pv1[2 * s2 + 1];
            }
            // z and h_hat
            u64 z0a[5], z1a[5], h0a[5], h1a[5];
#pragma unroll
            for (int s2 = 0; s2 < 5; ++s2) {
                u64 bz2 = ((const u64*)(sm + OFF_BZ2))[s2];
                u64 bh2 = ((const u64*)(sm + OFF_BH2))[s2];
                z0a[s2] = bz2; z1a[s2] = bz2;
                h0a[s2] = bh2; h1a[s2] = bh2;
            }
            const float* WZb = sm + OFF_WZ2;
            const float* WHb = sm + OFF_WH2;
#pragma unroll
            for (int j = 0; j < 20; ++j) {
                u64 o0 = pack2(j < 10 ? av0[j] : pv0[j - 10]);
                u64 o1 = pack2(j < 10 ? av1[j] : pv1[j - 10]);
                u64 q0 = (j < 10) ? o0 : pack2(rp0[j - 10]);
                u64 q1 = (j < 10) ? o1 : pack2(rp1[j - 10]);
                ulonglong2 za = *(const ulonglong2*)(WZb + j * 12);
                ulonglong2 zb = *(const ulonglong2*)(WZb + j * 12 + 4);
                u64 zc = *(const u64*)(WZb + j * 12 + 8);
                ulonglong2 ha = *(const ulonglong2*)(WHb + j * 12);
                ulonglong2 hb = *(const ulonglong2*)(WHb + j * 12 + 4);
                u64 hc = *(const u64*)(WHb + j * 12 + 8);
                z0a[0] = ffma2(o0, za.x, z0a[0]); z1a[0] = ffma2(o1, za.x, z1a[0]);
                z0a[1] = ffma2(o0, za.y, z0a[1]); z1a[1] = ffma2(o1, za.y, z1a[1]);
                z0a[2] = ffma2(o0, zb.x, z0a[2]); z1a[2] = ffma2(o1, zb.x, z1a[2]);
                z0a[3] = ffma2(o0, zb.y, z0a[3]); z1a[3] = ffma2(o1, zb.y, z1a[3]);
                z0a[4] = ffma2(o0, zc,   z0a[4]); z1a[4] = ffma2(o1, zc,   z1a[4]);
                h0a[0] = ffma2(q0, ha.x, h0a[0]); h1a[0] = ffma2(q1, ha.x, h1a[0]);
                h0a[1] = ffma2(q0, ha.y, h0a[1]); h1a[1] = ffma2(q1, ha.y, h1a[1]);
                h0a[2] = ffma2(q0, hb.x, h0a[2]); h1a[2] = ffma2(q1, hb.x, h1a[2]);
                h0a[3] = ffma2(q0, hb.y, h0a[3]); h1a[3] = ffma2(q1, hb.y, h1a[3]);
                h0a[4] = ffma2(q0, hc,   h0a[4]); h1a[4] = ffma2(q1, hc,   h1a[4]);
            }
#pragma unroll
            for (int s2 = 0; s2 < 5; ++s2) {
                float zx, zy, hx, hy;
                unpack2(z0a[s2], zx, zy);
                unpack2(h0a[s2], hx, hy);
                zx = sigf(zx); zy = sigf(zy);
                hx = tanh_(hx); hy = tanh_(hy);
                sm[OFF_P + (2 * s2) * 1120 + idx0] =
                    pv0[2 * s2] + zx * (hx - pv0[2 * s2]);
                sm[OFF_P + (2 * s2 + 1) * 1120 + idx0] =
                    pv0[2 * s2 + 1] + zy * (hy - pv0[2 * s2 + 1]);
                unpack2(z1a[s2], zx, zy);
                unpack2(h1a[s2], hx, hy);
                zx = sigf(zx); zy = sigf(zy);
                hx = tanh_(hx); hy = tanh_(hy);
                sm[OFF_P + (2 * s2) * 1120 + idx1] =
                    pv1[2 * s2] + zx * (hx - pv1[2 * s2]);
                sm[OFF_P + (2 * s2 + 1) * 1120 + idx1] =
                    pv1[2 * s2 + 1] + zy * (hy - pv1[2 * s2 + 1]);
            }
        }
        __syncthreads();
    }

    // ---- output ----
#pragma unroll 1
    for (int task = t; task < BB_ * N_; task += TPB) {
        int bb = task / N_, n = task - bb * N_;
        int idx = bb * N_ + n;
        float an = annotation[b0 * N_ + idx];
        float o = sm[OFF_BO2];
#pragma unroll 2
        for (int s = 0; s < 10; ++s) {
            float a0 = sm[OFF_BO1 + s];
#pragma unroll
            for (int j = 0; j < 10; ++j)
                a0 += sm[OFF_P + j * 1120 + idx] * sm[OFF_WO1 + s * 11 + j];
            a0 += an * sm[OFF_WO1 + s * 11 + 10];
            o += tanh_(a0) * sm[OFF_WO2 + s];
        }
        out[b0 * N_ + idx] = o;
    }
}

extern "C" void kernel_launch(void* const* d_in, const int* in_sizes, int n_in,
                              void* d_out, int out_size) {
    const float* annotation = (const float*)d_in[0];
    const float* A    = (const float*)d_in[1];
    const float* W_in = (const float*)d_in[2];
    const float* b_in = (const float*)d_in[3];
    const float* Wr   = (const float*)d_in[4];
    const float* br   = (const float*)d_in[5];
    const float* Wz   = (const float*)d_in[6];
    const float* bz   = (const float*)d_in[7];
    const float* Wh   = (const float*)d_in[8];
    const float* bh   = (const float*)d_in[9];
    const float* Wo1  = (const float*)d_in[10];
    const float* bo1  = (const float*)d_in[11];
    const float* Wo2  = (const float*)d_in[12];
    const float* bo2  = (const float*)d_in[13];
    float* out = (float*)d_out;

    const int smem_bytes = SMEM_FLOATS * (int)sizeof(float);
    cudaFuncSetAttribute(ggnn_kernel,
                         cudaFuncAttributeMaxDynamicSharedMemorySize, smem_bytes);
    ggnn_kernel<<<B_ / BB_, TPB, smem_bytes>>>(
        annotation, A, W_in, b_in, Wr, br, Wz, bz, Wh, bh,
        Wo1, bo1, Wo2, bo2, out);
}